// round 12
// baseline (speedup 1.0000x reference)
#include <cuda_runtime.h>
#include <cuda_fp16.h>
#include <cstdint>

// LinearAttentionCell with T=1 reduces algebraically to out = x @ Wv^T.
// R12: MLP-burst GEMM. R3-R11 all pinned at ~12us because only ~32B/thread
// of DRAM loads were ever in flight (Little's law needs ~18KB/SM for 8TB/s;
// we had ~1KB/SM -> 1.5TB/s observed, every pipe <45%, issue ~19%).
// Fix: each CTA issues its ENTIRE working set (8 W float4 + 8 x float4 per
// thread = 256B/thread in flight) in one burst, converts into full-K fp16
// smem tiles, ONE __syncthreads, then an uninterrupted ldsm+MMA sweep.
// Numerics (R11-validated): x*w ~= xh*wh + xh*(wl*2^11)*2^-11, fp32 acc.

#define KDIM 2048
#define NDIM 2048
#define MDIM 64
#define NT   64
#define SPLITK 16
#define KCH  128
#define KSTEPS 8      // k16 steps per CTA
#define GT   256      // 8 warps: 2 wrow(m32) x 4 wcol(n16)
#define WLSC  2048.0f
#define WLINV (1.0f/2048.0f)

__device__ __forceinline__ uint32_t f16x2(float hi_e, float lo_e) {
    // packs: low 16 = f16(lo_e), high 16 = f16(hi_e)
    uint32_t r;
    asm("cvt.rn.f16x2.f32 %0, %1, %2;" : "=r"(r) : "f"(hi_e), "f"(lo_e));
    return r;
}

// split float4 of w into fp16 hi words + fp16 (lo*2^11) words
__device__ __forceinline__ void splitw4(float4 v, uint32_t& h01, uint32_t& h23,
                                        uint32_t& l01, uint32_t& l23) {
    h01 = f16x2(v.y, v.x);
    h23 = f16x2(v.w, v.z);
    float2 fa = __half22float2(*reinterpret_cast<__half2*>(&h01));
    float2 fb = __half22float2(*reinterpret_cast<__half2*>(&h23));
    l01 = f16x2((v.y - fa.y) * WLSC, (v.x - fa.x) * WLSC);
    l23 = f16x2((v.w - fb.y) * WLSC, (v.z - fb.x) * WLSC);
}

__device__ __forceinline__ void mma_f16(float* d, const uint32_t* a,
                                        uint32_t b0, uint32_t b1) {
    asm volatile(
        "mma.sync.aligned.m16n8k16.row.col.f32.f16.f16.f32 "
        "{%0,%1,%2,%3}, {%4,%5,%6,%7}, {%8,%9}, {%0,%1,%2,%3};"
        : "+f"(d[0]), "+f"(d[1]), "+f"(d[2]), "+f"(d[3])
        : "r"(a[0]), "r"(a[1]), "r"(a[2]), "r"(a[3]), "r"(b0), "r"(b1));
}

__device__ __forceinline__ void ldsm4(uint32_t* r, uint32_t addr) {
    asm volatile(
        "ldmatrix.sync.aligned.m8n8.x4.shared.b16 {%0,%1,%2,%3}, [%4];"
        : "=r"(r[0]), "=r"(r[1]), "=r"(r[2]), "=r"(r[3]) : "r"(addr));
}

__global__ __launch_bounds__(GT, 2)
void gemm_kernel(const float* __restrict__ x, const float* __restrict__ Wv,
                 float* __restrict__ out) {
    // fp16 tiles, each [64 rows x 16 k] = 2KB, 16B-chunk XOR swizzle.
    // Full K chunk resident: no stage double-buffering, one barrier total.
    __shared__ __align__(16) uint8_t AH[KSTEPS][2048];   // x fp16
    __shared__ __align__(16) uint8_t WH[KSTEPS][2048];   // w-hi fp16
    __shared__ __align__(16) uint8_t WL[KSTEPS][2048];   // w-lo*2^11 fp16

    const int tid  = threadIdx.x;
    const int lane = tid & 31;
    const int wid  = tid >> 5;
    const int wrow = wid >> 2;     // m32 group 0..1
    const int wcol = wid & 3;      // n16 group 0..3
    const int g  = lane >> 2;
    const int tt = lane & 3;

    const int n0 = blockIdx.x * NT;
    const int k0 = blockIdx.y * KCH;

    // ---- shared ingress mapping: thread -> (row r, 4-float k chunk kq) ----
    const int r   = tid >> 2;           // 0..63
    const int kq  = (tid & 3) * 4;      // 0,4,8,12 within 16-float kstep
    const int hq  = kq >> 3;            // 16B half
    const int off8 = (kq & 4) ? 8 : 0;
    const int sts_off = r * 32 + (((hq ^ (r >> 2)) & 1) << 4) + off8;

    const float* xp   = x  + (size_t)r * KDIM + k0 + kq;
    const float* wptr = Wv + (size_t)(n0 + r) * KDIM + k0 + kq;

    // ---- burst phase: ALL loads in flight at once (MLP = 16 x 16B/thread) ----
    float4 xr[KSTEPS], wr[KSTEPS];
#pragma unroll
    for (int i = 0; i < KSTEPS; i++)
        xr[i] = *reinterpret_cast<const float4*>(xp + i * 16);
#pragma unroll
    for (int i = 0; i < KSTEPS; i++)
        wr[i] = *reinterpret_cast<const float4*>(wptr + i * 16);

    // convert x -> AH tiles (frees xr)
#pragma unroll
    for (int i = 0; i < KSTEPS; i++) {
        uint32_t h01 = f16x2(xr[i].y, xr[i].x);
        uint32_t h23 = f16x2(xr[i].w, xr[i].z);
        *reinterpret_cast<uint2*>(&AH[i][sts_off]) = make_uint2(h01, h23);
    }
    // split w -> WH/WL tiles (frees wr)
#pragma unroll
    for (int i = 0; i < KSTEPS; i++) {
        uint32_t h01, h23, l01, l23;
        splitw4(wr[i], h01, h23, l01, l23);
        *reinterpret_cast<uint2*>(&WH[i][sts_off]) = make_uint2(h01, h23);
        *reinterpret_cast<uint2*>(&WL[i][sts_off]) = make_uint2(l01, l23);
    }

    __syncthreads();   // the only barrier

    // ---- ldmatrix lane offsets (R11-validated) ----
    const int am0 = (wrow * 2 + 0) * 16 + (lane & 15);
    const int am1 = am0 + 16;
    const int akh = lane >> 4;
    const uint32_t aoff0 = am0 * 32 + (((akh ^ (am0 >> 2)) & 1) << 4);
    const uint32_t aoff1 = am1 * 32 + (((akh ^ (am1 >> 2)) & 1) << 4);
    const int nl   = ((lane >> 4) & 1) * 8 + (lane & 7);
    const int bkh  = (lane >> 3) & 1;
    const int brow = wcol * 16 + nl;
    const uint32_t boff = brow * 32 + (((bkh ^ (brow >> 2)) & 1) << 4);

    float acch[2][2][4], accl[2][2][4];
#pragma unroll
    for (int a = 0; a < 2; a++)
#pragma unroll
        for (int b = 0; b < 2; b++)
#pragma unroll
            for (int c = 0; c < 4; c++) { acch[a][b][c] = 0.f; accl[a][b][c] = 0.f; }

    // ---- uninterrupted MMA sweep over all 8 ksteps ----
#pragma unroll
    for (int ks = 0; ks < KSTEPS; ks++) {
        uint32_t a0[4], a1[4], bh[4], bl[4];
        ldsm4(a0, (uint32_t)__cvta_generic_to_shared(&AH[ks][0]) + aoff0);
        ldsm4(a1, (uint32_t)__cvta_generic_to_shared(&AH[ks][0]) + aoff1);
        ldsm4(bh, (uint32_t)__cvta_generic_to_shared(&WH[ks][0]) + boff);
        ldsm4(bl, (uint32_t)__cvta_generic_to_shared(&WL[ks][0]) + boff);

        // 8 MMAs, 8 independent accumulators
        mma_f16(acch[0][0], a0, bh[0], bh[1]);
        mma_f16(acch[0][1], a0, bh[2], bh[3]);
        mma_f16(acch[1][0], a1, bh[0], bh[1]);
        mma_f16(acch[1][1], a1, bh[2], bh[3]);
        mma_f16(accl[0][0], a0, bl[0], bl[1]);
        mma_f16(accl[0][1], a0, bl[2], bl[3]);
        mma_f16(accl[1][0], a1, bl[0], bl[1]);
        mma_f16(accl[1][1], a1, bl[2], bl[3]);
    }

    // ---- epilogue: combine scales, split-K via vector atomics ----
#pragma unroll
    for (int mb = 0; mb < 2; mb++) {
#pragma unroll
        for (int nf = 0; nf < 2; nf++) {
            float v0 = acch[mb][nf][0] + accl[mb][nf][0] * WLINV;
            float v1 = acch[mb][nf][1] + accl[mb][nf][1] * WLINV;
            float v2 = acch[mb][nf][2] + accl[mb][nf][2] * WLINV;
            float v3 = acch[mb][nf][3] + accl[mb][nf][3] * WLINV;
            int m = (wrow * 2 + mb) * 16 + g;
            int n = n0 + wcol * 16 + nf * 8 + 2 * tt;
            atomicAdd(reinterpret_cast<float2*>(&out[m * NDIM + n]),
                      make_float2(v0, v1));
            atomicAdd(reinterpret_cast<float2*>(&out[(m + 8) * NDIM + n]),
                      make_float2(v2, v3));
        }
    }
}

extern "C" void kernel_launch(void* const* d_in, const int* in_sizes, int n_in,
                              void* d_out, int out_size) {
    // inputs: 0=x [64,1,2048] f32, 1=Wq, 2=bq, 3=Wk, 4=bk, 5=Wv [2048,2048], 6=pos
    const float* x  = (const float*)d_in[0];
    const float* Wv = (const float*)d_in[5];
    float* out = (float*)d_out;

    cudaMemsetAsync(out, 0, (size_t)MDIM * NDIM * sizeof(float));
    dim3 grid(NDIM / NT, SPLITK);   // 32 x 16 = 512 CTAs
    gemm_kernel<<<grid, GT>>>(x, Wv, out);

    (void)in_sizes; (void)n_in; (void)out_size;
}

// round 13
// speedup vs baseline: 1.1154x; 1.1154x over previous
#include <cuda_runtime.h>
#include <cuda_fp16.h>
#include <cstdint>

// LinearAttentionCell with T=1 reduces algebraically to out = x @ Wv^T.
// R13: SINGLE-product fp16 GEMM. R11 measured rel_err 2.078e-4 with only x
// quantized to fp16; quantizing w too adds an independent incoherent error
// -> predicted sqrt(2)*2.08e-4 ~ 2.9e-4, comfortably under the 1e-3 gate.
// out ~= f16(x) * f16(w), fp32 accum. This halves MMAs (262K -> 131K),
// halves W smem tiles/ldsm, and cuts the split ALU by 3x -- attacking the
// per-warp total-operation count, the only lever not yet pulled (occupancy,
// MLP, smem structure, MAC count via 2-product all proved neutral).

#define KDIM 2048
#define NDIM 2048
#define MDIM 64
#define NT   64
#define SPLITK 16
#define KCH  128
#define KSTEPS 8      // k16 steps per CTA
#define GT   256      // 8 warps: 2 wrow(m32) x 4 wcol(n16)

__device__ __forceinline__ uint32_t f16x2(float hi_e, float lo_e) {
    // packs: low 16 = f16(lo_e), high 16 = f16(hi_e)
    uint32_t r;
    asm("cvt.rn.f16x2.f32 %0, %1, %2;" : "=r"(r) : "f"(hi_e), "f"(lo_e));
    return r;
}

__device__ __forceinline__ void mma_f16(float* d, const uint32_t* a,
                                        uint32_t b0, uint32_t b1) {
    asm volatile(
        "mma.sync.aligned.m16n8k16.row.col.f32.f16.f16.f32 "
        "{%0,%1,%2,%3}, {%4,%5,%6,%7}, {%8,%9}, {%0,%1,%2,%3};"
        : "+f"(d[0]), "+f"(d[1]), "+f"(d[2]), "+f"(d[3])
        : "r"(a[0]), "r"(a[1]), "r"(a[2]), "r"(a[3]), "r"(b0), "r"(b1));
}

__device__ __forceinline__ void ldsm4(uint32_t* r, uint32_t addr) {
    asm volatile(
        "ldmatrix.sync.aligned.m8n8.x4.shared.b16 {%0,%1,%2,%3}, [%4];"
        : "=r"(r[0]), "=r"(r[1]), "=r"(r[2]), "=r"(r[3]) : "r"(addr));
}

__global__ __launch_bounds__(GT, 3)
void gemm_kernel(const float* __restrict__ x, const float* __restrict__ Wv,
                 float* __restrict__ out) {
    // fp16 tiles, each [64 rows x 16 k] = 2KB, 16B-chunk XOR swizzle.
    __shared__ __align__(16) uint8_t AH[KSTEPS][2048];   // x fp16
    __shared__ __align__(16) uint8_t WH[KSTEPS][2048];   // w fp16

    const int tid  = threadIdx.x;
    const int lane = tid & 31;
    const int wid  = tid >> 5;
    const int wrow = wid >> 2;     // m32 group 0..1
    const int wcol = wid & 3;      // n16 group 0..3
    const int g  = lane >> 2;
    const int tt = lane & 3;

    const int n0 = blockIdx.x * NT;
    const int k0 = blockIdx.y * KCH;

    // ---- shared ingress mapping: thread -> (row r, 4-float k chunk kq) ----
    const int r   = tid >> 2;           // 0..63
    const int kq  = (tid & 3) * 4;      // 0,4,8,12 within 16-float kstep
    const int hq  = kq >> 3;            // 16B half
    const int off8 = (kq & 4) ? 8 : 0;
    const int sts_off = r * 32 + (((hq ^ (r >> 2)) & 1) << 4) + off8;

    const float* xp   = x  + (size_t)r * KDIM + k0 + kq;
    const float* wptr = Wv + (size_t)(n0 + r) * KDIM + k0 + kq;

    // ---- burst 1: x slice (8 LDG.128 in flight), convert, store ----
    {
        float4 xr[KSTEPS];
#pragma unroll
        for (int i = 0; i < KSTEPS; i++)
            xr[i] = *reinterpret_cast<const float4*>(xp + i * 16);
#pragma unroll
        for (int i = 0; i < KSTEPS; i++) {
            uint32_t h01 = f16x2(xr[i].y, xr[i].x);
            uint32_t h23 = f16x2(xr[i].w, xr[i].z);
            *reinterpret_cast<uint2*>(&AH[i][sts_off]) = make_uint2(h01, h23);
        }
    }
    // ---- burst 2: W slice (8 LDG.128 in flight), convert, store ----
    {
        float4 wr[KSTEPS];
#pragma unroll
        for (int i = 0; i < KSTEPS; i++)
            wr[i] = *reinterpret_cast<const float4*>(wptr + i * 16);
#pragma unroll
        for (int i = 0; i < KSTEPS; i++) {
            uint32_t h01 = f16x2(wr[i].y, wr[i].x);
            uint32_t h23 = f16x2(wr[i].w, wr[i].z);
            *reinterpret_cast<uint2*>(&WH[i][sts_off]) = make_uint2(h01, h23);
        }
    }

    __syncthreads();   // the only barrier

    // ---- ldmatrix lane offsets (R11/R12-validated) ----
    const int am0 = (wrow * 2 + 0) * 16 + (lane & 15);
    const int am1 = am0 + 16;
    const int akh = lane >> 4;
    const uint32_t aoff0 = am0 * 32 + (((akh ^ (am0 >> 2)) & 1) << 4);
    const uint32_t aoff1 = am1 * 32 + (((akh ^ (am1 >> 2)) & 1) << 4);
    const int nl   = ((lane >> 4) & 1) * 8 + (lane & 7);
    const int bkh  = (lane >> 3) & 1;
    const int brow = wcol * 16 + nl;
    const uint32_t boff = brow * 32 + (((bkh ^ (brow >> 2)) & 1) << 4);

    float acc[2][2][4];
#pragma unroll
    for (int a = 0; a < 2; a++)
#pragma unroll
        for (int b = 0; b < 2; b++)
#pragma unroll
            for (int c = 0; c < 4; c++) acc[a][b][c] = 0.f;

    // ---- uninterrupted MMA sweep: 8 ksteps x (3 ldsm + 4 mma) ----
#pragma unroll
    for (int ks = 0; ks < KSTEPS; ks++) {
        uint32_t a0[4], a1[4], bh[4];
        ldsm4(a0, (uint32_t)__cvta_generic_to_shared(&AH[ks][0]) + aoff0);
        ldsm4(a1, (uint32_t)__cvta_generic_to_shared(&AH[ks][0]) + aoff1);
        ldsm4(bh, (uint32_t)__cvta_generic_to_shared(&WH[ks][0]) + boff);

        mma_f16(acc[0][0], a0, bh[0], bh[1]);
        mma_f16(acc[0][1], a0, bh[2], bh[3]);
        mma_f16(acc[1][0], a1, bh[0], bh[1]);
        mma_f16(acc[1][1], a1, bh[2], bh[3]);
    }

    // ---- epilogue: split-K via vector atomics ----
#pragma unroll
    for (int mb = 0; mb < 2; mb++) {
#pragma unroll
        for (int nf = 0; nf < 2; nf++) {
            int m = (wrow * 2 + mb) * 16 + g;
            int n = n0 + wcol * 16 + nf * 8 + 2 * tt;
            atomicAdd(reinterpret_cast<float2*>(&out[m * NDIM + n]),
                      make_float2(acc[mb][nf][0], acc[mb][nf][1]));
            atomicAdd(reinterpret_cast<float2*>(&out[(m + 8) * NDIM + n]),
                      make_float2(acc[mb][nf][2], acc[mb][nf][3]));
        }
    }
}

extern "C" void kernel_launch(void* const* d_in, const int* in_sizes, int n_in,
                              void* d_out, int out_size) {
    // inputs: 0=x [64,1,2048] f32, 1=Wq, 2=bq, 3=Wk, 4=bk, 5=Wv [2048,2048], 6=pos
    const float* x  = (const float*)d_in[0];
    const float* Wv = (const float*)d_in[5];
    float* out = (float*)d_out;

    cudaMemsetAsync(out, 0, (size_t)MDIM * NDIM * sizeof(float));
    dim3 grid(NDIM / NT, SPLITK);   // 32 x 16 = 512 CTAs
    gemm_kernel<<<grid, GT>>>(x, Wv, out);

    (void)in_sizes; (void)n_in; (void)out_size;
}